// round 8
// baseline (speedup 1.0000x reference)
#include <cuda_runtime.h>
#include <stdint.h>

#define BB 64
#define TT 512
#define UU 256
#define VH 128   // v-columns per CTA (cluster of 2 CTAs per batch)

__device__ float g_ll[BB];

// ---------------------------------------------------------------------------
// helpers
// ---------------------------------------------------------------------------
__device__ __forceinline__ uint32_t s2u(const void* p) {
    uint32_t r;
    asm("{ .reg .u64 t; cvta.to.shared.u64 t, %1; cvt.u32.u64 %0, t; }" : "=r"(r) : "l"(p));
    return r;
}
__device__ __forceinline__ unsigned long long pack2(float lo, float hi) {
    unsigned long long r;
    asm("mov.b64 %0, {%1, %2};" : "=l"(r) : "f"(lo), "f"(hi));
    return r;
}

struct __align__(16) Smem {
    float ea[UU];           // exp(alpha - C), indexed by v (==u)
    float recv[2][UU];      // peer partials, st.async landing zone (1KB stride)
    float pl0[2];           // local partial P for u=0 (per ring slot)
    float spot[2];          // pot[b,t,0] (per ring slot)
    float calpha;           // broadcast of alpha[0] at init
    unsigned long long mb[2];  // mbarriers: count=1 (local u0 arrive.expect_tx)
    float red[8];
    float sscore;
};

// ---------------------------------------------------------------------------
// k_forward: one 2-CTA cluster per batch; CTA rank r owns v in [r*128,(r+1)*128).
// Thread = u (0..255). E[v][u] for my v-half in 64 packed-f32x2 registers.
// Both CTAs compute full alpha redundantly; per step each sends its 256
// partial sums to the peer via st.async with mbarrier complete_tx (no second
// bar.sync, no remote-arrive hop). Scale C lags one step so its update needs
// only bar1-ordered local smem.
// ---------------------------------------------------------------------------
__global__ __launch_bounds__(256, 1) __cluster_dims__(2, 1, 1)
void k_forward(const float* __restrict__ pot,     // [B,T,U]
               const int*   __restrict__ tags,    // [B,T]
               const int*   __restrict__ seqlen,  // [B]
               const float* __restrict__ trans)   // [U,U]
{
    __shared__ Smem sm;
    const int u    = threadIdx.x;
    const int rank = blockIdx.x & 1;
    const int b    = blockIdx.x >> 1;
    const int lane = u & 31;
    const int wid  = u >> 5;
    const int L    = seqlen[b];

    // ---- init: mbarriers (count=1) + prime ring slot 0 for the lagged C ----
    if (u == 0) {
        asm volatile("mbarrier.init.shared.b64 [%0], 1;" :: "r"(s2u(&sm.mb[0])) : "memory");
        asm volatile("mbarrier.init.shared.b64 [%0], 1;" :: "r"(s2u(&sm.mb[1])) : "memory");
        sm.pl0[0]     = 0.5f;   // p0 + r0 = 1 -> log = 0 at t=1
        sm.recv[0][0] = 0.5f;
        sm.spot[0]    = 0.0f;
    }
    __syncthreads();
    asm volatile("barrier.cluster.arrive.aligned;" ::: "memory");

    // ---- load E[v][u] = exp(trans[v][u]) for my v-half into 64 f32x2 regs ----
    unsigned long long em[VH / 2];
    {
        const float* tb = trans + rank * VH * UU + u;   // column u, rows = my v-half
        #pragma unroll
        for (int j = 0; j < VH / 2; j++) {
            float f0 = __expf(__ldg(tb + (2 * j) * UU));
            float f1 = __expf(__ldg(tb + (2 * j + 1) * UU));
            em[j] = pack2(f0, f1);
        }
    }

    // finish cluster barrier (peer mbarriers + primes visible before any st.async)
    asm volatile("barrier.cluster.wait.aligned;" ::: "memory");

    // ---- path score (rank 0 only; CTA-uniform branch) ----
    if (rank == 0) {
        float sc = 0.0f;
        for (int t = u; t < L; t += 256) {
            int tg = __ldg(&tags[b * TT + t]);
            sc += __ldg(&pot[(b * TT + t) * UU + tg]);
            if (t >= 1) {
                int tp = __ldg(&tags[b * TT + t - 1]);
                sc += __ldg(&trans[tp * UU + tg]);
            }
        }
        #pragma unroll
        for (int o = 16; o; o >>= 1) sc += __shfl_xor_sync(0xffffffffu, sc, o);
        if (lane == 0) sm.red[wid] = sc;
        __syncthreads();
        if (u == 0)
            sm.sscore = (sm.red[0] + sm.red[1]) + (sm.red[2] + sm.red[3])
                      + (sm.red[4] + sm.red[5]) + (sm.red[6] + sm.red[7]);
    }

    // ---- alpha init + scale C (identical in both CTAs) ----
    float alpha = pot[b * TT * UU + u];
    if (u == 0) sm.calpha = alpha;
    __syncthreads();
    float C     = sm.calpha;   // scale used for this step's exp
    float Cprev = C;           // C that generated the data in the prev ring slot

    // hoisted addresses
    const uint32_t ea_base = s2u(&sm.ea[0]) + (uint32_t)(rank * VH) * 4u;
    const uint32_t l_mb    = s2u(&sm.mb[0]);
    const uint32_t l_recvu = s2u(&sm.recv[0][0]) + (uint32_t)u * 4u;
    uint32_t r_recvu, r_mb;
    asm("mapa.shared::cluster.u32 %0, %1, %2;" : "=r"(r_recvu)
        : "r"(l_recvu), "r"(rank ^ 1));
    asm("mapa.shared::cluster.u32 %0, %1, %2;" : "=r"(r_mb) : "r"(l_mb), "r"(rank ^ 1));

    // ---- forward recursion ----
    // ring: buf = t&1 (starts at 1). Barrier mb[buf] used every 2 steps;
    // parity flips when wrapping from buf0 back to buf1.
    uint32_t bufoff = 1024u;   // buf * 1024 bytes
    uint32_t mboff  = 8u;      // buf * 8 bytes
    uint32_t par    = 0u;
    for (int t = 1; t < L; t++) {
        float pot_t = __ldg(&pot[(b * TT + t) * UU + u]);
        float e = __expf(alpha - C);
        sm.ea[u] = e;
        __syncthreads();                                    // bar1: ea + prev-slot scalars

        if (u == 0)
            asm volatile("mbarrier.arrive.expect_tx.shared.b64 _, [%0], %1;"
                         :: "r"(l_mb + mboff), "r"(1024u) : "memory");

        // lagged C update: alpha_{t-1}[0] from prev ring slot (bar1-ordered)
        const int buf = (int)(bufoff >> 10);
        const int pbi = buf ^ 1;
        float Cn = Cprev + __logf(sm.pl0[pbi] + sm.recv[pbi][0]) + sm.spot[pbi];

        // partial S over my v-half: P_u = sum_v ea[v] * E[v][u]  (f32x2 packed)
        unsigned long long acc0 = 0ull, acc1 = 0ull;
        #pragma unroll
        for (int i = 0; i < VH / 4; i++) {                  // 32 iters: 4 v each
            unsigned long long a0, a1;
            asm volatile("ld.shared.v2.u64 {%0, %1}, [%2];"
                         : "=l"(a0), "=l"(a1) : "r"(ea_base + 16u * i));
            asm("fma.rn.f32x2 %0, %1, %2, %0;" : "+l"(acc0) : "l"(a0), "l"(em[2 * i]));
            asm("fma.rn.f32x2 %0, %1, %2, %0;" : "+l"(acc1) : "l"(a1), "l"(em[2 * i + 1]));
        }
        unsigned long long accs;
        asm("add.rn.f32x2 %0, %1, %2;" : "=l"(accs) : "l"(acc0), "l"(acc1));
        float plo, phi;
        asm("mov.b64 {%0, %1}, %2;" : "=f"(plo), "=f"(phi) : "l"(accs));
        float P = plo + phi;

        // send partial to peer recv[buf][u]; tx counts on PEER's mb[buf]
        asm volatile("st.async.shared::cluster.mbarrier::complete_tx::bytes.b32 [%0], %1, [%2];"
                     :: "r"(r_recvu + bufoff), "r"(__float_as_uint(P)),
                        "r"(r_mb + mboff) : "memory");
        if (u == 0) { sm.pl0[buf] = P; sm.spot[buf] = pot_t; }

        // wait: local arrive (u0) + 1024 tx bytes from peer
        {
            uint32_t done = 0;
            while (!done) {
                asm volatile(
                    "{ .reg .pred p;\n\t"
                    "mbarrier.try_wait.parity.acquire.cluster.shared::cta.b64 p, [%1], %2, 0x989680;\n\t"
                    "selp.b32 %0, 1, 0, p; }"
                    : "=r"(done) : "r"(l_mb + mboff), "r"(par) : "memory");
            }
        }

        float R;
        asm("ld.shared.f32 %0, [%1];" : "=f"(R) : "r"(l_recvu + bufoff));
        alpha = C + __logf(P + R) + pot_t;                  // + commutative: identical in both CTAs
        Cprev = C;
        C     = Cn;

        // advance ring: flip parity when wrapping buf0 -> buf1
        par    ^= ((bufoff ^ 1024u) >> 10);
        bufoff ^= 1024u;
        mboff  ^= 8u;
    }

    // all st.async traffic complete before any CTA exits
    asm volatile("barrier.cluster.arrive.aligned;" ::: "memory");
    asm volatile("barrier.cluster.wait.aligned;" ::: "memory");

    // ---- finalize: logsumexp(alpha) - score (rank 0 only) ----
    if (rank == 0) {
        float m = alpha;
        #pragma unroll
        for (int o = 16; o; o >>= 1) m = fmaxf(m, __shfl_xor_sync(0xffffffffu, m, o));
        if (lane == 0) sm.red[wid] = m;
        __syncthreads();
        m = fmaxf(fmaxf(fmaxf(sm.red[0], sm.red[1]), fmaxf(sm.red[2], sm.red[3])),
                  fmaxf(fmaxf(sm.red[4], sm.red[5]), fmaxf(sm.red[6], sm.red[7])));
        __syncthreads();
        float ee = __expf(alpha - m);
        #pragma unroll
        for (int o = 16; o; o >>= 1) ee += __shfl_xor_sync(0xffffffffu, ee, o);
        if (lane == 0) sm.red[wid] = ee;
        __syncthreads();
        if (u == 0) {
            float s = (sm.red[0] + sm.red[1]) + (sm.red[2] + sm.red[3])
                    + (sm.red[4] + sm.red[5]) + (sm.red[6] + sm.red[7]);
            g_ll[b] = sm.sscore - (m + __logf(s));
        }
    }
}

// ---------------------------------------------------------------------------
// k_final: out = -mean(ll)
// ---------------------------------------------------------------------------
__global__ void k_final(float* __restrict__ out) {
    __shared__ float r[2];
    float v = g_ll[threadIdx.x];   // 64 threads
    #pragma unroll
    for (int o = 16; o; o >>= 1) v += __shfl_xor_sync(0xffffffffu, v, o);
    if ((threadIdx.x & 31) == 0) r[threadIdx.x >> 5] = v;
    __syncthreads();
    if (threadIdx.x == 0) out[0] = -(r[0] + r[1]) * (1.0f / (float)BB);
}

// ---------------------------------------------------------------------------
extern "C" void kernel_launch(void* const* d_in, const int* in_sizes, int n_in,
                              void* d_out, int out_size) {
    (void)in_sizes; (void)n_in; (void)out_size;
    const float* pot    = (const float*)d_in[0];
    const int*   tags   = (const int*)  d_in[1];
    const int*   seqlen = (const int*)  d_in[2];
    const float* trans  = (const float*)d_in[3];
    float* out = (float*)d_out;

    k_forward<<<BB * 2, UU>>>(pot, tags, seqlen, trans);   // 64 clusters of 2 CTAs
    k_final<<<1, BB>>>(out);
}

// round 9
// speedup vs baseline: 1.7374x; 1.7374x over previous
#include <cuda_runtime.h>
#include <stdint.h>

#define BB 64
#define TT 512
#define UU 256
#define VH 128   // v-columns per CTA (cluster of 2 CTAs per batch)

__device__ float g_ll[BB];

// ---------------------------------------------------------------------------
__device__ __forceinline__ uint32_t s2u(const void* p) {
    uint32_t r;
    asm("{ .reg .u64 t; cvta.to.shared.u64 t, %1; cvt.u32.u64 %0, t; }" : "=r"(r) : "l"(p));
    return r;
}
__device__ __forceinline__ unsigned long long pack2(float lo, float hi) {
    unsigned long long r;
    asm("mov.b64 %0, {%1, %2};" : "=l"(r) : "f"(lo), "f"(hi));
    return r;
}
__device__ __forceinline__ float rcp_approx(float v) {
    float r;
    asm("rcp.approx.f32 %0, %1;" : "=f"(r) : "f"(v));
    return r;
}

struct __align__(16) Smem {
    float ea[UU];              // x_{t-1} (scaled exp-space alpha), indexed by v
    float recv[2][UU];         // peer partials, st.async landing zone (1KB stride)
    float c0;                  // broadcast of pot[b,0,0]
    unsigned long long mb[2];  // mbarriers: count=1 (local u0 arrive.expect_tx)
    float red[8];
    float sscore;
};

// ---------------------------------------------------------------------------
// k_forward: one 2-CTA cluster per batch; CTA rank r owns v in [r*128,(r+1)*128).
// Thread = u. E[v][u] for my v-half in 64 packed-f32x2 registers.
// Exp-space recursion: x_t = (P+R) * pe_t * q_t  (NO log/exp on the critical
// chain; pe prefetched 2 steps deep; q = rcp of last step's x[0], read from
// ea[0] after bar1). Scale bookkeeping Lq accumulated off-path.
// ---------------------------------------------------------------------------
__global__ __launch_bounds__(256, 1) __cluster_dims__(2, 1, 1)
void k_forward(const float* __restrict__ pot,     // [B,T,U]
               const int*   __restrict__ tags,    // [B,T]
               const int*   __restrict__ seqlen,  // [B]
               const float* __restrict__ trans)   // [U,U]
{
    __shared__ Smem sm;
    const int u    = threadIdx.x;
    const int rank = blockIdx.x & 1;
    const int b    = blockIdx.x >> 1;
    const int lane = u & 31;
    const int wid  = u >> 5;
    const int L    = seqlen[b];

    if (u == 0) {
        asm volatile("mbarrier.init.shared.b64 [%0], 1;" :: "r"(s2u(&sm.mb[0])) : "memory");
        asm volatile("mbarrier.init.shared.b64 [%0], 1;" :: "r"(s2u(&sm.mb[1])) : "memory");
    }
    __syncthreads();
    asm volatile("barrier.cluster.arrive.aligned;" ::: "memory");

    // ---- E[v][u] = exp(trans[v][u]) for my v-half -> 64 f32x2 registers ----
    unsigned long long em[VH / 2];
    {
        const float* tb = trans + rank * VH * UU + u;
        #pragma unroll
        for (int j = 0; j < VH / 2; j++) {
            float f0 = __expf(__ldg(tb + (2 * j) * UU));
            float f1 = __expf(__ldg(tb + (2 * j + 1) * UU));
            em[j] = pack2(f0, f1);
        }
    }
    asm volatile("barrier.cluster.wait.aligned;" ::: "memory");

    // ---- path score (rank 0 only) ----
    if (rank == 0) {
        float sc = 0.0f;
        for (int t = u; t < L; t += 256) {
            int tg = __ldg(&tags[b * TT + t]);
            sc += __ldg(&pot[(b * TT + t) * UU + tg]);
            if (t >= 1) {
                int tp = __ldg(&tags[b * TT + t - 1]);
                sc += __ldg(&trans[tp * UU + tg]);
            }
        }
        #pragma unroll
        for (int o = 16; o; o >>= 1) sc += __shfl_xor_sync(0xffffffffu, sc, o);
        if (lane == 0) sm.red[wid] = sc;
        __syncthreads();
        if (u == 0)
            sm.sscore = (sm.red[0] + sm.red[1]) + (sm.red[2] + sm.red[3])
                      + (sm.red[4] + sm.red[5]) + (sm.red[6] + sm.red[7]);
    }

    // ---- init: x_0 = exp(pot0 - C0), Lq = C0 ----
    float p0 = pot[b * TT * UU + u];
    if (u == 0) sm.c0 = p0;
    __syncthreads();
    float C0 = sm.c0;
    float x  = __expf(p0 - C0);     // x_0[0] == 1 by construction
    float Lq = C0;

    // ---- pot pipeline (2-deep): pe for t, raw for t+1 ----
    float pe   = __expf(__ldg(&pot[(b * TT + 1) * UU + u]));   // pe for t=1
    float potR = __ldg(&pot[(b * TT + 2) * UU + u]);           // raw for t=2

    // hoisted addresses
    const uint32_t ea_base = s2u(&sm.ea[0]) + (uint32_t)(rank * VH) * 4u;
    const uint32_t ea0     = s2u(&sm.ea[0]);
    const uint32_t l_mb    = s2u(&sm.mb[0]);
    const uint32_t l_recvu = s2u(&sm.recv[0][0]) + (uint32_t)u * 4u;
    uint32_t r_recvu, r_mb;
    asm("mapa.shared::cluster.u32 %0, %1, %2;" : "=r"(r_recvu)
        : "r"(l_recvu), "r"(rank ^ 1));
    asm("mapa.shared::cluster.u32 %0, %1, %2;" : "=r"(r_mb) : "r"(l_mb), "r"(rank ^ 1));

    // ---- forward recursion (exp space) ----
    // ring: buf = t&1 (starts 1); barrier reused every 2 steps, parity flips on wrap.
    uint32_t bufoff = 1024u, mboff = 8u, par = 0u;
    for (int t = 1; t < L; t++) {
        sm.ea[u] = x;
        __syncthreads();                                    // bar1: x published

        if (u == 0)
            asm volatile("mbarrier.arrive.expect_tx.shared.b64 _, [%0], %1;"
                         :: "r"(l_mb + mboff), "r"(1024u) : "memory");

        // off-path: scale from last step's x[0]; pot pipeline advance
        float z;
        asm("ld.shared.f32 %0, [%1];" : "=f"(z) : "r"(ea0));
        float qn  = rcp_approx(z);
        Lq += __logf(z);
        float peN = __expf(potR);                           // pe for t+1
        int tn = t + 2; tn = (tn < TT) ? tn : (TT - 1);
        float potR2 = __ldg(&pot[(b * TT + tn) * UU + u]);  // raw for t+2

        // P_u = sum over my v-half of x[v] * E[v][u]  (f32x2 packed)
        unsigned long long acc0 = 0ull, acc1 = 0ull;
        #pragma unroll
        for (int i = 0; i < VH / 4; i++) {
            unsigned long long a0, a1;
            asm volatile("ld.shared.v2.u64 {%0, %1}, [%2];"
                         : "=l"(a0), "=l"(a1) : "r"(ea_base + 16u * i));
            asm("fma.rn.f32x2 %0, %1, %2, %0;" : "+l"(acc0) : "l"(a0), "l"(em[2 * i]));
            asm("fma.rn.f32x2 %0, %1, %2, %0;" : "+l"(acc1) : "l"(a1), "l"(em[2 * i + 1]));
        }
        unsigned long long accs;
        asm("add.rn.f32x2 %0, %1, %2;" : "=l"(accs) : "l"(acc0), "l"(acc1));
        float plo, phi;
        asm("mov.b64 {%0, %1}, %2;" : "=f"(plo), "=f"(phi) : "l"(accs));
        float P = plo + phi;

        // send partial to peer recv[buf][u]; tx counts on PEER's mb[buf]
        asm volatile("st.async.shared::cluster.mbarrier::complete_tx::bytes.b32 [%0], %1, [%2];"
                     :: "r"(r_recvu + bufoff), "r"(__float_as_uint(P)),
                        "r"(r_mb + mboff) : "memory");

        // wait: local arrive (u0) + 1024 tx bytes from peer
        {
            uint32_t done = 0;
            while (!done) {
                asm volatile(
                    "{ .reg .pred p;\n\t"
                    "mbarrier.try_wait.parity.acquire.cluster.shared::cta.b64 p, [%1], %2, 0x989680;\n\t"
                    "selp.b32 %0, 1, 0, p; }"
                    : "=r"(done) : "r"(l_mb + mboff), "r"(par) : "memory");
            }
        }

        float R;
        asm("ld.shared.f32 %0, [%1];" : "=f"(R) : "r"(l_recvu + bufoff));
        x = (P + R) * pe * qn;      // commutative sum: bitwise identical in both CTAs

        pe = peN; potR = potR2;     // rotate pipeline
        par    ^= ((bufoff ^ 1024u) >> 10);
        bufoff ^= 1024u;
        mboff  ^= 8u;
    }

    asm volatile("barrier.cluster.arrive.aligned;" ::: "memory");
    asm volatile("barrier.cluster.wait.aligned;" ::: "memory");

    // ---- finalize: logZ = Lq + log(sum_u x[u]); ll = score - logZ (rank 0) ----
    if (rank == 0) {
        float s = x;
        #pragma unroll
        for (int o = 16; o; o >>= 1) s += __shfl_xor_sync(0xffffffffu, s, o);
        if (lane == 0) sm.red[wid] = s;
        __syncthreads();
        if (u == 0) {
            float tot = (sm.red[0] + sm.red[1]) + (sm.red[2] + sm.red[3])
                      + (sm.red[4] + sm.red[5]) + (sm.red[6] + sm.red[7]);
            g_ll[b] = sm.sscore - (Lq + __logf(tot));
        }
    }
}

// ---------------------------------------------------------------------------
__global__ void k_final(float* __restrict__ out) {
    __shared__ float r[2];
    float v = g_ll[threadIdx.x];   // 64 threads
    #pragma unroll
    for (int o = 16; o; o >>= 1) v += __shfl_xor_sync(0xffffffffu, v, o);
    if ((threadIdx.x & 31) == 0) r[threadIdx.x >> 5] = v;
    __syncthreads();
    if (threadIdx.x == 0) out[0] = -(r[0] + r[1]) * (1.0f / (float)BB);
}

// ---------------------------------------------------------------------------
extern "C" void kernel_launch(void* const* d_in, const int* in_sizes, int n_in,
                              void* d_out, int out_size) {
    (void)in_sizes; (void)n_in; (void)out_size;
    const float* pot    = (const float*)d_in[0];
    const int*   tags   = (const int*)  d_in[1];
    const int*   seqlen = (const int*)  d_in[2];
    const float* trans  = (const float*)d_in[3];
    float* out = (float*)d_out;

    k_forward<<<BB * 2, UU>>>(pot, tags, seqlen, trans);   // 64 clusters of 2 CTAs
    k_final<<<1, BB>>>(out);
}